// round 16
// baseline (speedup 1.0000x reference)
#include <cuda_runtime.h>
#include <cuda_fp16.h>
#include <stdint.h>
#include <math.h>

#define B_   8
#define W_   1024
#define H_   16
#define D_   64
#define BH_  (B_ * H_)
#define NQKV (B_ * W_ * H_ * D_)        /* 8,388,608  */
#define NATT ((size_t)BH_ * W_ * W_)    /* 134,217,728 */

#define FLT_BIG 3.402823466e38f

// quantized (q_int - zp) values as fp16, layout [BH][W][D]
__device__ __half g_qh[NQKV];
__device__ __half g_kh[NQKV];
__device__ __half g_vh[NQKV];
// per-row softmax denominators: 1 / sum_k exp(fq'd score)
__device__ float g_rowinv[BH_ * W_];
// min/max accumulators (ordered-uint), slots: 0=q 1=k 2=v 3=scores 4=att 5=ctx
__device__ unsigned g_omin[6];
__device__ unsigned g_omax[6];

// ---------------- float <-> order-preserving uint ----------------
__device__ __forceinline__ unsigned f2o(float f) {
    unsigned u = __float_as_uint(f);
    return (u & 0x80000000u) ? ~u : (u | 0x80000000u);
}
__device__ __forceinline__ float o2f(unsigned u) {
    return (u & 0x80000000u) ? __uint_as_float(u & 0x7fffffffu)
                             : __uint_as_float(~u);
}

// ---------------- fake-quant helpers ----------------
__device__ __forceinline__ void get_sz(int slot, float& s, float& zp) {
    float mn = o2f(g_omin[slot]);
    float mx = o2f(g_omax[slot]);
    s  = fmaxf((mx - mn) / 255.0f, 1e-8f);
    zp = fminf(fmaxf(rintf(-128.0f - mn / s), -128.0f), 127.0f);
}
__device__ __forceinline__ float fq_q(float x, float inv_s, float zp) {
    return fminf(fmaxf(rintf(x * inv_s) + zp, -128.0f), 127.0f) - zp;
}
__device__ __forceinline__ float fq_code(float x, float inv_s, float zp) {
    return fminf(fmaxf(rintf(x * inv_s) + zp, -128.0f), 127.0f);
}

// ---------------- min/max commits ----------------
__device__ __forceinline__ void block_minmax_commit(float vmin, float vmax, int slot,
                                                    int tid, int nthreads) {
    #pragma unroll
    for (int o = 16; o; o >>= 1) {
        vmin = fminf(vmin, __shfl_xor_sync(0xffffffffu, vmin, o));
        vmax = fmaxf(vmax, __shfl_xor_sync(0xffffffffu, vmax, o));
    }
    __shared__ float smn[8], smx[8];
    int w = tid >> 5, l = tid & 31;
    int nw = (nthreads + 31) >> 5;
    if (l == 0) { smn[w] = vmin; smx[w] = vmax; }
    __syncthreads();
    if (w == 0) {
        vmin = (l < nw) ? smn[l] : FLT_BIG;
        vmax = (l < nw) ? smx[l] : -FLT_BIG;
        #pragma unroll
        for (int o = 4; o; o >>= 1) {
            vmin = fminf(vmin, __shfl_xor_sync(0xffffffffu, vmin, o));
            vmax = fmaxf(vmax, __shfl_xor_sync(0xffffffffu, vmax, o));
        }
        if (l == 0) {
            atomicMin(&g_omin[slot], f2o(vmin));
            atomicMax(&g_omax[slot], f2o(vmax));
        }
    }
    __syncthreads();
}

__device__ __forceinline__ void warp_minmax_commit(float vmin, float vmax, int slot, int lane) {
    #pragma unroll
    for (int o = 16; o; o >>= 1) {
        vmin = fminf(vmin, __shfl_xor_sync(0xffffffffu, vmin, o));
        vmax = fmaxf(vmax, __shfl_xor_sync(0xffffffffu, vmax, o));
    }
    if (lane == 0) {
        atomicMin(&g_omin[slot], f2o(vmin));
        atomicMax(&g_omax[slot], f2o(vmax));
    }
}

// ---------------- ldmatrix / mma / cp.async wrappers ----------------
__device__ __forceinline__ unsigned smem_u32(const void* p) {
    return (unsigned)__cvta_generic_to_shared(p);
}
__device__ __forceinline__ void ldsm_x4(unsigned a, unsigned& r0, unsigned& r1,
                                        unsigned& r2, unsigned& r3) {
    asm volatile("ldmatrix.sync.aligned.m8n8.x4.shared.b16 {%0,%1,%2,%3}, [%4];"
                 : "=r"(r0), "=r"(r1), "=r"(r2), "=r"(r3) : "r"(a));
}
__device__ __forceinline__ void ldsm_x2(unsigned a, unsigned& r0, unsigned& r1) {
    asm volatile("ldmatrix.sync.aligned.m8n8.x2.shared.b16 {%0,%1}, [%2];"
                 : "=r"(r0), "=r"(r1) : "r"(a));
}
__device__ __forceinline__ void ldsm_x4t(unsigned a, unsigned& r0, unsigned& r1,
                                         unsigned& r2, unsigned& r3) {
    asm volatile("ldmatrix.sync.aligned.m8n8.x4.trans.shared.b16 {%0,%1,%2,%3}, [%4];"
                 : "=r"(r0), "=r"(r1), "=r"(r2), "=r"(r3) : "r"(a));
}
__device__ __forceinline__ void mma16816(float* d, unsigned a0, unsigned a1,
                                         unsigned a2, unsigned a3,
                                         unsigned b0, unsigned b1) {
    asm volatile(
        "mma.sync.aligned.m16n8k16.row.col.f32.f16.f16.f32 "
        "{%0,%1,%2,%3}, {%4,%5,%6,%7}, {%8,%9}, {%0,%1,%2,%3};"
        : "+f"(d[0]), "+f"(d[1]), "+f"(d[2]), "+f"(d[3])
        : "r"(a0), "r"(a1), "r"(a2), "r"(a3), "r"(b0), "r"(b1));
}
__device__ __forceinline__ void cp_async16(unsigned dst, const void* src) {
    asm volatile("cp.async.cg.shared.global [%0], [%1], 16;"
                 :: "r"(dst), "l"(src));
}
__device__ __forceinline__ void cp_async_commit() {
    asm volatile("cp.async.commit_group;");
}
__device__ __forceinline__ void cp_async_wait0() {
    asm volatile("cp.async.wait_group 0;");
}

// ---------------- kernels ----------------
__global__ void k_init() {
    int i = threadIdx.x;
    if (i < 6) { g_omin[i] = 0xFFFFFFFFu; g_omax[i] = 0u; }
}

__global__ void __launch_bounds__(256) k_minmax3(const float4* __restrict__ q,
                                                 const float4* __restrict__ k,
                                                 const float4* __restrict__ v) {
    int slot = blockIdx.x >> 9;
    const float4* x = (slot == 0) ? q : (slot == 1) ? k : v;
    int n4 = NQKV / 4;
    float vmin = FLT_BIG, vmax = -FLT_BIG;
    for (int i = (blockIdx.x & 511) * 256 + threadIdx.x; i < n4; i += 512 * 256) {
        float4 f = x[i];
        vmin = fminf(vmin, fminf(fminf(f.x, f.y), fminf(f.z, f.w)));
        vmax = fmaxf(vmax, fmaxf(fmaxf(f.x, f.y), fmaxf(f.z, f.w)));
    }
    block_minmax_commit(vmin, vmax, slot, threadIdx.x, 256);
}

__global__ void __launch_bounds__(256) k_quant(const float* __restrict__ q,
                                               const float* __restrict__ k,
                                               const float* __restrict__ v) {
    float s0, z0, s1, z1, s2, z2;
    get_sz(0, s0, z0); get_sz(1, s1, z1); get_sz(2, s2, z2);
    float i0 = 1.0f / s0, i1 = 1.0f / s1, i2 = 1.0f / s2;

    int bw = blockIdx.x;
    int b = bw >> 10, w = bw & 1023;
    int t = threadIdx.x;
    int h = t >> 4, d4 = (t & 15) * 4;

    size_t src = ((size_t)bw * H_ + h) * D_ + d4;
    size_t dst = (((size_t)(b * H_ + h)) * W_ + w) * D_ + d4;

    union { __half2 h2; unsigned u; } p0, p1;

    float4 fv = *(const float4*)(q + src);
    p0.h2 = __floats2half2_rn(fq_q(fv.x, i0, z0), fq_q(fv.y, i0, z0));
    p1.h2 = __floats2half2_rn(fq_q(fv.z, i0, z0), fq_q(fv.w, i0, z0));
    *(uint2*)(g_qh + dst) = make_uint2(p0.u, p1.u);

    fv = *(const float4*)(k + src);
    p0.h2 = __floats2half2_rn(fq_q(fv.x, i1, z1), fq_q(fv.y, i1, z1));
    p1.h2 = __floats2half2_rn(fq_q(fv.z, i1, z1), fq_q(fv.w, i1, z1));
    *(uint2*)(g_kh + dst) = make_uint2(p0.u, p1.u);

    fv = *(const float4*)(v + src);
    p0.h2 = __floats2half2_rn(fq_q(fv.x, i2, z2), fq_q(fv.y, i2, z2));
    p1.h2 = __floats2half2_rn(fq_q(fv.z, i2, z2), fq_q(fv.w, i2, z2));
    *(uint2*)(g_vh + dst) = make_uint2(p0.u, p1.u);
}

// A: scores min/max ONLY (no store). CTA = 128x128 tile. grid (8,8,128).
// (round-12 proven config: 89us — FROZEN)
__global__ void __launch_bounds__(256) k_sminmax() {
    __shared__ uint4 At[128 * 8];
    __shared__ uint4 Kt[128 * 8];

    int bh = blockIdx.z;
    int q0 = blockIdx.y * 128, k0 = blockIdx.x * 128;
    int tid = threadIdx.x;

    const uint4* qsrc = (const uint4*)(g_qh + ((size_t)bh * W_ + q0) * D_);
    const uint4* ksrc = (const uint4*)(g_kh + ((size_t)bh * W_ + k0) * D_);
    #pragma unroll
    for (int i = 0; i < 4; i++) {
        int g = tid + i * 256;
        int r = g >> 3, c = g & 7;
        At[r * 8 + (c ^ (r & 7))] = qsrc[g];
        Kt[r * 8 + (c ^ (r & 7))] = ksrc[g];
    }
    __syncthreads();

    int wid = tid >> 5, l = tid & 31;
    int wm = wid >> 2, wn = wid & 3;

    float acc[4][4][4];
    #pragma unroll
    for (int i = 0; i < 4; i++)
        #pragma unroll
        for (int j = 0; j < 4; j++)
            #pragma unroll
            for (int e = 0; e < 4; e++) acc[i][j][e] = 0.0f;

    unsigned abase = smem_u32(At), kbase = smem_u32(Kt);

    #pragma unroll
    for (int kc = 0; kc < 4; kc++) {
        unsigned a[4][4];
        #pragma unroll
        for (int mi = 0; mi < 4; mi++) {
            int row = wm * 64 + mi * 16 + (l & 15);
            int ch  = kc * 2 + (l >> 4);
            ldsm_x4(abase + (row * 8 + (ch ^ (row & 7))) * 16,
                    a[mi][0], a[mi][1], a[mi][2], a[mi][3]);
        }
        unsigned bf[4][2];
        #pragma unroll
        for (int ni = 0; ni < 4; ni++) {
            int row = wn * 32 + ni * 8 + (l & 7);
            int ch  = kc * 2 + ((l >> 3) & 1);
            ldsm_x2(kbase + (row * 8 + (ch ^ (row & 7))) * 16, bf[ni][0], bf[ni][1]);
        }
        #pragma unroll
        for (int mi = 0; mi < 4; mi++)
            #pragma unroll
            for (int ni = 0; ni < 4; ni++)
                mma16816(acc[mi][ni], a[mi][0], a[mi][1], a[mi][2], a[mi][3],
                         bf[ni][0], bf[ni][1]);
    }

    float s0, z0, s1, z1;
    get_sz(0, s0, z0); get_sz(1, s1, z1);
    float sc = s0 * s1 * 0.125f;

    float vmin = FLT_BIG, vmax = -FLT_BIG;
    #pragma unroll
    for (int mi = 0; mi < 4; mi++)
        #pragma unroll
        for (int ni = 0; ni < 4; ni++)
            #pragma unroll
            for (int e = 0; e < 4; e++) {
                float v = acc[mi][ni][e] * sc;
                vmin = fminf(vmin, v);
                vmax = fmaxf(vmax, v);
            }
    block_minmax_commit(vmin, vmax, 3, tid, 256);
}

// B: recompute scores per 128-row q-tile; softmax denominators WITHOUT max
// subtraction. 8 warps, warp tile = 16 rows x 64 cols. Double-buffered K.
// K B-fragments batched via ldsm_x4 (pairs of n-tiles). grid (8, BH).
__global__ void __launch_bounds__(256) k_rowstats2() {
    __shared__ uint4 Qt[128 * 8];      // 16KB
    __shared__ uint4 Kt[2][64 * 8];    // 2 x 8KB

    int q0 = blockIdx.x * 128;
    int bh = blockIdx.y;
    int tid = threadIdx.x;
    int wid = tid >> 5, l = tid & 31;

    const uint4* qsrc = (const uint4*)(g_qh + ((size_t)bh * W_ + q0) * D_);
    #pragma unroll
    for (int i = 0; i < 4; i++) {
        int g = tid + i * 256;
        int r = g >> 3, c = g & 7;
        Qt[r * 8 + (c ^ (r & 7))] = qsrc[g];
    }

    float s0, z0, s1, z1, s3, z3;
    get_sz(0, s0, z0); get_sz(1, s1, z1); get_sz(3, s3, z3);
    float sc = s0 * s1 * 0.125f;
    float inv3 = 1.0f / s3;

    unsigned qbase = smem_u32(Qt);
    const uint4* ksrc = (const uint4*)(g_kh + (size_t)bh * W_ * D_);

    auto load_k = [&](int kk, int buf) {
        unsigned kb = smem_u32(Kt[buf]);
        #pragma unroll
        for (int i = 0; i < 2; i++) {
            int g = tid + i * 256;
            int r = g >> 3, c = g & 7;
            cp_async16(kb + (r * 8 + (c ^ (r & 7))) * 16, ksrc + (size_t)kk * 512 + g);
        }
        cp_async_commit();
    };

    load_k(0, 0);

    float sum0 = 0.0f, sum1 = 0.0f;
    float mx0 = -FLT_BIG, mx1 = -FLT_BIG, mn0 = FLT_BIG, mn1 = FLT_BIG;

    for (int kk = 0; kk < 16; kk++) {
        int cur = kk & 1;
        cp_async_wait0();
        __syncthreads();
        if (kk < 15) load_k(kk + 1, cur ^ 1);

        unsigned kbase = smem_u32(Kt[cur]);
        float acc[8][4];
        #pragma unroll
        for (int ni = 0; ni < 8; ni++)
            #pragma unroll
            for (int e = 0; e < 4; e++) acc[ni][e] = 0.0f;

        #pragma unroll
        for (int kc = 0; kc < 4; kc++) {
            unsigned a0, a1, a2, a3;
            {
                int row = wid * 16 + (l & 15);
                int ch  = kc * 2 + (l >> 4);
                ldsm_x4(qbase + (row * 8 + (ch ^ (row & 7))) * 16, a0, a1, a2, a3);
            }
            #pragma unroll
            for (int np = 0; np < 4; np++) {    // pairs of n-tiles via ldsm_x4
                unsigned b0, b1, b2, b3;
                int row = np * 16 + ((l & 16) >> 1) + (l & 7);
                int ch  = kc * 2 + ((l >> 3) & 1);
                ldsm_x4(kbase + (row * 8 + (ch ^ (row & 7))) * 16, b0, b1, b2, b3);
                mma16816(acc[np * 2],     a0, a1, a2, a3, b0, b1);
                mma16816(acc[np * 2 + 1], a0, a1, a2, a3, b2, b3);
            }
        }

        #pragma unroll
        for (int ni = 0; ni < 8; ni++) {
            float v00 = (fq_code(acc[ni][0] * sc, inv3, z3) - z3) * s3;
            float v01 = (fq_code(acc[ni][1] * sc, inv3, z3) - z3) * s3;
            float v10 = (fq_code(acc[ni][2] * sc, inv3, z3) - z3) * s3;
            float v11 = (fq_code(acc[ni][3] * sc, inv3, z3) - z3) * s3;
            sum0 += __expf(v00) + __expf(v01);
            sum1 += __expf(v10) + __expf(v11);
            mx0 = fmaxf(mx0, fmaxf(v00, v01)); mn0 = fminf(mn0, fminf(v00, v01));
            mx1 = fmaxf(mx1, fmaxf(v10, v11)); mn1 = fminf(mn1, fminf(v10, v11));
        }
    }

    // single cross-lane reduction (4 lanes per row)
    #pragma unroll
    for (int o = 1; o <= 2; o <<= 1) {
        sum0 += __shfl_xor_sync(0xffffffffu, sum0, o);
        sum1 += __shfl_xor_sync(0xffffffffu, sum1, o);
        mx0 = fmaxf(mx0, __shfl_xor_sync(0xffffffffu, mx0, o));
        mx1 = fmaxf(mx1, __shfl_xor_sync(0xffffffffu, mx1, o));
        mn0 = fminf(mn0, __shfl_xor_sync(0xffffffffu, mn0, o));
        mn1 = fminf(mn1, __shfl_xor_sync(0xffffffffu, mn1, o));
    }
    float inv0 = 1.0f / sum0, inv1 = 1.0f / sum1;

    // att row extremes (exp monotone)
    float amin = fminf(__expf(mn0) * inv0, __expf(mn1) * inv1);
    float amax = fmaxf(__expf(mx0) * inv0, __expf(mx1) * inv1);
    warp_minmax_commit(amin, amax, 4, l);

    if ((l & 3) == 0) {
        int r0 = q0 + wid * 16 + (l >> 2);
        g_rowinv[(size_t)bh * W_ + r0]     = inv0;
        g_rowinv[(size_t)bh * W_ + r0 + 8] = inv1;
    }
}

// C: fused recompute-scores -> softmax (no max subtraction) -> fq att (write)
// -> att @ V -> ctx. 8 warps, warp tile = 16 q-rows x 64 cols; att ints
// repacked in registers. Double-buffered K/V. K via ldsm_x4 pairs, V via
// ldsm_x4.trans pairs. smem 48KB exact -> warp commits.
__global__ void __launch_bounds__(256) k_fusedav(float* __restrict__ att,
                                                 float* __restrict__ ctx) {
    __shared__ uint4 Qt[128 * 8];
    __shared__ uint4 Kt[2][64 * 8];
    __shared__ uint4 Vt[2][64 * 8];

    int q0 = blockIdx.x * 128;
    int bh = blockIdx.y;
    int b = bh >> 4, h = bh & 15;
    int tid = threadIdx.x;
    int wid = tid >> 5, l = tid & 31;

    const uint4* qsrc = (const uint4*)(g_qh + ((size_t)bh * W_ + q0) * D_);
    #pragma unroll
    for (int i = 0; i < 4; i++) {
        int g = tid + i * 256;
        int r = g >> 3, c = g & 7;
        Qt[r * 8 + (c ^ (r & 7))] = qsrc[g];
    }

    float s0, z0, s1, z1, s3, z3, s_a, zp_a, s_v, zp_v;
    get_sz(0, s0, z0); get_sz(1, s1, z1); get_sz(3, s3, z3);
    get_sz(4, s_a, zp_a); get_sz(2, s_v, zp_v);
    float sc = s0 * s1 * 0.125f;
    float inv3 = 1.0f / s3;
    float inv_a = 1.0f / s_a;

    // this warp's rows: r = wid*16 + (l>>2), and r+8
    float inv0 = g_rowinv[(size_t)bh * W_ + q0 + wid * 16 + (l >> 2)];
    float inv1 = g_rowinv[(size_t)bh * W_ + q0 + wid * 16 + (l >> 2) + 8];

    float cacc[8][4];
    #pragma unroll
    for (int i = 0; i < 8; i++)
        #pragma unroll
        for (int e = 0; e < 4; e++) cacc[i][e] = 0.0f;

    unsigned qbase = smem_u32(Qt);
    const uint4* ksrc = (const uint4*)(g_kh + (size_t)bh * W_ * D_);
    const uint4* vsrc = (const uint4*)(g_vh + (size_t)bh * W_ * D_);

    auto load_kv = [&](int kk, int buf) {
        unsigned kb = smem_u32(Kt[buf]);
        unsigned vb = smem_u32(Vt[buf]);
        #pragma unroll
        for (int i = 0; i < 2; i++) {
            int g = tid + i * 256;
            int r = g >> 3, c = g & 7;
            unsigned off = (r * 8 + (c ^ (r & 7))) * 16;
            cp_async16(kb + off, ksrc + (size_t)kk * 512 + g);
            cp_async16(vb + off, vsrc + (size_t)kk * 512 + g);
        }
        cp_async_commit();
    };

    load_kv(0, 0);

    float* att_base = att + ((size_t)bh * W_ + q0 + wid * 16 + (l >> 2)) * W_ + (l & 3) * 2;

    for (int kk = 0; kk < 16; kk++) {
        int cur = kk & 1;
        cp_async_wait0();
        __syncthreads();
        if (kk < 15) load_kv(kk + 1, cur ^ 1);

        unsigned kbase = smem_u32(Kt[cur]);
        unsigned vbase = smem_u32(Vt[cur]);

        // S = Q x K^T chunk: 16 rows x 64 cols per warp
        float sfr[8][4];
        #pragma unroll
        for (int ni = 0; ni < 8; ni++)
            #pragma unroll
            for (int e = 0; e < 4; e++) sfr[ni][e] = 0.0f;

        #pragma unroll
        for (int kc = 0; kc < 4; kc++) {
            unsigned a0, a1, a2, a3;
            {
                int row = wid * 16 + (l & 15);
                int ch  = kc * 2 + (l >> 4);
                ldsm_x4(qbase + (row * 8 + (ch ^ (row & 7))) * 16, a0, a1, a2, a3);
            }
            #pragma unroll
            for (int np = 0; np < 4; np++) {    // pairs of n-tiles via ldsm_x4
                unsigned b0, b1, b2, b3;
                int row = np * 16 + ((l & 16) >> 1) + (l & 7);
                int ch  = kc * 2 + ((l >> 3) & 1);
                ldsm_x4(kbase + (row * 8 + (ch ^ (row & 7))) * 16, b0, b1, b2, b3);
                mma16816(sfr[np * 2],     a0, a1, a2, a3, b0, b1);
                mma16816(sfr[np * 2 + 1], a0, a1, a2, a3, b2, b3);
            }
        }

        // softmax + fq att; write att; repack ints into AV A-fragments
        unsigned amma[4][4];
        #pragma unroll
        for (int ni = 0; ni < 8; ni++) {
            float e0 = __expf((fq_code(sfr[ni][0] * sc, inv3, z3) - z3) * s3) * inv0;
            float e1 = __expf((fq_code(sfr[ni][1] * sc, inv3, z3) - z3) * s3) * inv0;
            float e2 = __expf((fq_code(sfr[ni][2] * sc, inv3, z3) - z3) * s3) * inv1;
            float e3 = __expf((fq_code(sfr[ni][3] * sc, inv3, z3) - z3) * s3) * inv1;
            float j0 = fq_q(e0, inv_a, zp_a), j1 = fq_q(e1, inv_a, zp_a);
            float j2 = fq_q(e2, inv_a, zp_a), j3 = fq_q(e3, inv_a, zp_a);
            *(float2*)(att_base + kk * 64 + ni * 8)            = make_float2(j0 * s_a, j1 * s_a);
            *(float2*)(att_base + 8 * W_ + kk * 64 + ni * 8)   = make_float2(j2 * s_a, j3 * s_a);
            union { __half2 h2; unsigned u; } plo, phi;
            plo.h2 = __floats2half2_rn(j0, j1);
            phi.h2 = __floats2half2_rn(j2, j3);
            int kc = ni >> 1;
            if ((ni & 1) == 0) { amma[kc][0] = plo.u; amma[kc][1] = phi.u; }
            else               { amma[kc][2] = plo.u; amma[kc][3] = phi.u; }
        }

        // ctx += att(16x64) x V(64x64); V fragments batched via ldsm_x4.trans
        #pragma unroll
        for (int kc = 0; kc < 4; kc++) {
            #pragma unroll
            for (int np = 0; np < 4; np++) {
                unsigned b0, b1, b2, b3;
                int rv = kc * 16 + (l & 15);
                int ch = np * 2 + (l >> 4);
                ldsm_x4t(vbase + (rv * 8 + (ch ^ (rv & 7))) * 16, b0, b1, b2, b3);
                mma16816(cacc[np * 2],     amma[kc][0], amma[kc][1], amma[kc][2], amma[kc][3], b0, b1);
                mma16816(cacc[np * 2 + 1], amma[kc][0], amma[kc][1], amma[kc][2], amma[kc][3], b2, b3);
            }
        }
    }

    float scv = s_a * s_v;
    float vmin = FLT_BIG, vmax = -FLT_BIG;
    int r0 = q0 + wid * 16 + (l >> 2);
    #pragma unroll
    for (int nt = 0; nt < 8; nt++) {
        int d = nt * 8 + (l & 3) * 2;
        float v0 = cacc[nt][0] * scv, v1 = cacc[nt][1] * scv;
        float v2 = cacc[nt][2] * scv, v3 = cacc[nt][3] * scv;
        vmin = fminf(vmin, fminf(fminf(v0, v1), fminf(v2, v3)));
        vmax = fmaxf(vmax, fmaxf(fmaxf(v0, v1), fmaxf(v2, v3)));
        size_t o0 = ((size_t)(b * W_ + r0) * H_ + h) * D_ + d;
        size_t o1 = ((size_t)(b * W_ + r0 + 8) * H_ + h) * D_ + d;
        *(float2*)(ctx + o0) = make_float2(v0, v1);
        *(float2*)(ctx + o1) = make_float2(v2, v3);
    }
    warp_minmax_commit(vmin, vmax, 5, l);
}

__global__ void __launch_bounds__(256) k_fqctx(float* __restrict__ ctx) {
    float s5, z5;
    get_sz(5, s5, z5);
    float inv5 = 1.0f / s5;
    for (int i = blockIdx.x * blockDim.x + threadIdx.x; i < NQKV; i += gridDim.x * blockDim.x) {
        ctx[i] = fq_q(ctx[i], inv5, z5) * s5;
    }
}

// ---------------- launch ----------------
extern "C" void kernel_launch(void* const* d_in, const int* in_sizes, int n_in,
                              void* d_out, int out_size) {
    const float* q = (const float*)d_in[0];
    const float* k = (const float*)d_in[1];
    const float* v = (const float*)d_in[2];

    float* ctx = (float*)d_out;
    float* att = (float*)d_out + ((size_t)out_size - NATT);

    k_init<<<1, 32>>>();

    k_minmax3<<<1536, 256>>>((const float4*)q, (const float4*)k, (const float4*)v);

    k_quant<<<B_ * W_, 256>>>(q, k, v);

    dim3 ga(8, 8, BH_);
    k_sminmax<<<ga, 256>>>();

    dim3 gb(8, BH_);
    k_rowstats2<<<gb, 256>>>();

    dim3 gc(8, BH_);
    k_fusedav<<<gc, 256>>>(att, ctx);

    k_fqctx<<<2048, 256>>>(ctx);
}

// round 17
// speedup vs baseline: 1.0218x; 1.0218x over previous
#include <cuda_runtime.h>
#include <cuda_fp16.h>
#include <stdint.h>
#include <math.h>

#define B_   8
#define W_   1024
#define H_   16
#define D_   64
#define BH_  (B_ * H_)
#define NQKV (B_ * W_ * H_ * D_)        /* 8,388,608  */
#define NATT ((size_t)BH_ * W_ * W_)    /* 134,217,728 */

#define FLT_BIG 3.402823466e38f

// quantized (q_int - zp) values as fp16, layout [BH][W][D]
__device__ __half g_qh[NQKV];
__device__ __half g_kh[NQKV];
__device__ __half g_vh[NQKV];
// per-row softmax denominators: 1 / sum_k exp(fq'd score)
__device__ float g_rowinv[BH_ * W_];
// min/max accumulators (ordered-uint), slots: 0=q 1=k 2=v 3=scores 4=att 5=ctx
__device__ unsigned g_omin[6];
__device__ unsigned g_omax[6];

// ---------------- float <-> order-preserving uint ----------------
__device__ __forceinline__ unsigned f2o(float f) {
    unsigned u = __float_as_uint(f);
    return (u & 0x80000000u) ? ~u : (u | 0x80000000u);
}
__device__ __forceinline__ float o2f(unsigned u) {
    return (u & 0x80000000u) ? __uint_as_float(u & 0x7fffffffu)
                             : __uint_as_float(~u);
}

// ---------------- fake-quant helpers ----------------
__device__ __forceinline__ void get_sz(int slot, float& s, float& zp) {
    float mn = o2f(g_omin[slot]);
    float mx = o2f(g_omax[slot]);
    s  = fmaxf((mx - mn) / 255.0f, 1e-8f);
    zp = fminf(fmaxf(rintf(-128.0f - mn / s), -128.0f), 127.0f);
}
__device__ __forceinline__ float fq_q(float x, float inv_s, float zp) {
    return fminf(fmaxf(rintf(x * inv_s) + zp, -128.0f), 127.0f) - zp;
}
__device__ __forceinline__ float fq_code(float x, float inv_s, float zp) {
    return fminf(fmaxf(rintf(x * inv_s) + zp, -128.0f), 127.0f);
}

// ---------------- min/max commits ----------------
__device__ __forceinline__ void block_minmax_commit(float vmin, float vmax, int slot,
                                                    int tid, int nthreads) {
    #pragma unroll
    for (int o = 16; o; o >>= 1) {
        vmin = fminf(vmin, __shfl_xor_sync(0xffffffffu, vmin, o));
        vmax = fmaxf(vmax, __shfl_xor_sync(0xffffffffu, vmax, o));
    }
    __shared__ float smn[8], smx[8];
    int w = tid >> 5, l = tid & 31;
    int nw = (nthreads + 31) >> 5;
    if (l == 0) { smn[w] = vmin; smx[w] = vmax; }
    __syncthreads();
    if (w == 0) {
        vmin = (l < nw) ? smn[l] : FLT_BIG;
        vmax = (l < nw) ? smx[l] : -FLT_BIG;
        #pragma unroll
        for (int o = 4; o; o >>= 1) {
            vmin = fminf(vmin, __shfl_xor_sync(0xffffffffu, vmin, o));
            vmax = fmaxf(vmax, __shfl_xor_sync(0xffffffffu, vmax, o));
        }
        if (l == 0) {
            atomicMin(&g_omin[slot], f2o(vmin));
            atomicMax(&g_omax[slot], f2o(vmax));
        }
    }
    __syncthreads();
}

__device__ __forceinline__ void warp_minmax_commit(float vmin, float vmax, int slot, int lane) {
    #pragma unroll
    for (int o = 16; o; o >>= 1) {
        vmin = fminf(vmin, __shfl_xor_sync(0xffffffffu, vmin, o));
        vmax = fmaxf(vmax, __shfl_xor_sync(0xffffffffu, vmax, o));
    }
    if (lane == 0) {
        atomicMin(&g_omin[slot], f2o(vmin));
        atomicMax(&g_omax[slot], f2o(vmax));
    }
}

// ---------------- ldmatrix / mma / cp.async wrappers ----------------
__device__ __forceinline__ unsigned smem_u32(const void* p) {
    return (unsigned)__cvta_generic_to_shared(p);
}
__device__ __forceinline__ void ldsm_x4(unsigned a, unsigned& r0, unsigned& r1,
                                        unsigned& r2, unsigned& r3) {
    asm volatile("ldmatrix.sync.aligned.m8n8.x4.shared.b16 {%0,%1,%2,%3}, [%4];"
                 : "=r"(r0), "=r"(r1), "=r"(r2), "=r"(r3) : "r"(a));
}
__device__ __forceinline__ void ldsm_x2(unsigned a, unsigned& r0, unsigned& r1) {
    asm volatile("ldmatrix.sync.aligned.m8n8.x2.shared.b16 {%0,%1}, [%2];"
                 : "=r"(r0), "=r"(r1) : "r"(a));
}
__device__ __forceinline__ void ldsm_x2t(unsigned a, unsigned& r0, unsigned& r1) {
    asm volatile("ldmatrix.sync.aligned.m8n8.x2.trans.shared.b16 {%0,%1}, [%2];"
                 : "=r"(r0), "=r"(r1) : "r"(a));
}
__device__ __forceinline__ void mma16816(float* d, unsigned a0, unsigned a1,
                                         unsigned a2, unsigned a3,
                                         unsigned b0, unsigned b1) {
    asm volatile(
        "mma.sync.aligned.m16n8k16.row.col.f32.f16.f16.f32 "
        "{%0,%1,%2,%3}, {%4,%5,%6,%7}, {%8,%9}, {%0,%1,%2,%3};"
        : "+f"(d[0]), "+f"(d[1]), "+f"(d[2]), "+f"(d[3])
        : "r"(a0), "r"(a1), "r"(a2), "r"(a3), "r"(b0), "r"(b1));
}
__device__ __forceinline__ void cp_async16(unsigned dst, const void* src) {
    asm volatile("cp.async.cg.shared.global [%0], [%1], 16;"
                 :: "r"(dst), "l"(src));
}
__device__ __forceinline__ void cp_async_commit() {
    asm volatile("cp.async.commit_group;");
}
__device__ __forceinline__ void cp_async_wait0() {
    asm volatile("cp.async.wait_group 0;");
}
// streaming (evict-first) float2 store — keeps K/V resident in L2
__device__ __forceinline__ void stg_cs_f2(float* p, float x, float y) {
    asm volatile("st.global.cs.v2.f32 [%0], {%1, %2};"
                 :: "l"(p), "f"(x), "f"(y) : "memory");
}

// ---------------- kernels ----------------
__global__ void k_init() {
    int i = threadIdx.x;
    if (i < 6) { g_omin[i] = 0xFFFFFFFFu; g_omax[i] = 0u; }
}

__global__ void __launch_bounds__(256) k_minmax3(const float4* __restrict__ q,
                                                 const float4* __restrict__ k,
                                                 const float4* __restrict__ v) {
    int slot = blockIdx.x >> 9;
    const float4* x = (slot == 0) ? q : (slot == 1) ? k : v;
    int n4 = NQKV / 4;
    float vmin = FLT_BIG, vmax = -FLT_BIG;
    for (int i = (blockIdx.x & 511) * 256 + threadIdx.x; i < n4; i += 512 * 256) {
        float4 f = x[i];
        vmin = fminf(vmin, fminf(fminf(f.x, f.y), fminf(f.z, f.w)));
        vmax = fmaxf(vmax, fmaxf(fmaxf(f.x, f.y), fmaxf(f.z, f.w)));
    }
    block_minmax_commit(vmin, vmax, slot, threadIdx.x, 256);
}

__global__ void __launch_bounds__(256) k_quant(const float* __restrict__ q,
                                               const float* __restrict__ k,
                                               const float* __restrict__ v) {
    float s0, z0, s1, z1, s2, z2;
    get_sz(0, s0, z0); get_sz(1, s1, z1); get_sz(2, s2, z2);
    float i0 = 1.0f / s0, i1 = 1.0f / s1, i2 = 1.0f / s2;

    int bw = blockIdx.x;
    int b = bw >> 10, w = bw & 1023;
    int t = threadIdx.x;
    int h = t >> 4, d4 = (t & 15) * 4;

    size_t src = ((size_t)bw * H_ + h) * D_ + d4;
    size_t dst = (((size_t)(b * H_ + h)) * W_ + w) * D_ + d4;

    union { __half2 h2; unsigned u; } p0, p1;

    float4 fv = *(const float4*)(q + src);
    p0.h2 = __floats2half2_rn(fq_q(fv.x, i0, z0), fq_q(fv.y, i0, z0));
    p1.h2 = __floats2half2_rn(fq_q(fv.z, i0, z0), fq_q(fv.w, i0, z0));
    *(uint2*)(g_qh + dst) = make_uint2(p0.u, p1.u);

    fv = *(const float4*)(k + src);
    p0.h2 = __floats2half2_rn(fq_q(fv.x, i1, z1), fq_q(fv.y, i1, z1));
    p1.h2 = __floats2half2_rn(fq_q(fv.z, i1, z1), fq_q(fv.w, i1, z1));
    *(uint2*)(g_kh + dst) = make_uint2(p0.u, p1.u);

    fv = *(const float4*)(v + src);
    p0.h2 = __floats2half2_rn(fq_q(fv.x, i2, z2), fq_q(fv.y, i2, z2));
    p1.h2 = __floats2half2_rn(fq_q(fv.z, i2, z2), fq_q(fv.w, i2, z2));
    *(uint2*)(g_vh + dst) = make_uint2(p0.u, p1.u);
}

// A: scores min/max ONLY (no store). CTA = 128x128 tile. grid (8,8,128).
// (round-12 proven config: 89us — FROZEN)
__global__ void __launch_bounds__(256) k_sminmax() {
    __shared__ uint4 At[128 * 8];
    __shared__ uint4 Kt[128 * 8];

    int bh = blockIdx.z;
    int q0 = blockIdx.y * 128, k0 = blockIdx.x * 128;
    int tid = threadIdx.x;

    const uint4* qsrc = (const uint4*)(g_qh + ((size_t)bh * W_ + q0) * D_);
    const uint4* ksrc = (const uint4*)(g_kh + ((size_t)bh * W_ + k0) * D_);
    #pragma unroll
    for (int i = 0; i < 4; i++) {
        int g = tid + i * 256;
        int r = g >> 3, c = g & 7;
        At[r * 8 + (c ^ (r & 7))] = qsrc[g];
        Kt[r * 8 + (c ^ (r & 7))] = ksrc[g];
    }
    __syncthreads();

    int wid = tid >> 5, l = tid & 31;
    int wm = wid >> 2, wn = wid & 3;

    float acc[4][4][4];
    #pragma unroll
    for (int i = 0; i < 4; i++)
        #pragma unroll
        for (int j = 0; j < 4; j++)
            #pragma unroll
            for (int e = 0; e < 4; e++) acc[i][j][e] = 0.0f;

    unsigned abase = smem_u32(At), kbase = smem_u32(Kt);

    #pragma unroll
    for (int kc = 0; kc < 4; kc++) {
        unsigned a[4][4];
        #pragma unroll
        for (int mi = 0; mi < 4; mi++) {
            int row = wm * 64 + mi * 16 + (l & 15);
            int ch  = kc * 2 + (l >> 4);
            ldsm_x4(abase + (row * 8 + (ch ^ (row & 7))) * 16,
                    a[mi][0], a[mi][1], a[mi][2], a[mi][3]);
        }
        unsigned bf[4][2];
        #pragma unroll
        for (int ni = 0; ni < 4; ni++) {
            int row = wn * 32 + ni * 8 + (l & 7);
            int ch  = kc * 2 + ((l >> 3) & 1);
            ldsm_x2(kbase + (row * 8 + (ch ^ (row & 7))) * 16, bf[ni][0], bf[ni][1]);
        }
        #pragma unroll
        for (int mi = 0; mi < 4; mi++)
            #pragma unroll
            for (int ni = 0; ni < 4; ni++)
                mma16816(acc[mi][ni], a[mi][0], a[mi][1], a[mi][2], a[mi][3],
                         bf[ni][0], bf[ni][1]);
    }

    float s0, z0, s1, z1;
    get_sz(0, s0, z0); get_sz(1, s1, z1);
    float sc = s0 * s1 * 0.125f;

    float vmin = FLT_BIG, vmax = -FLT_BIG;
    #pragma unroll
    for (int mi = 0; mi < 4; mi++)
        #pragma unroll
        for (int ni = 0; ni < 4; ni++)
            #pragma unroll
            for (int e = 0; e < 4; e++) {
                float v = acc[mi][ni][e] * sc;
                vmin = fminf(vmin, v);
                vmax = fmaxf(vmax, v);
            }
    block_minmax_commit(vmin, vmax, 3, tid, 256);
}

// B: recompute scores per 128-row q-tile; softmax denominators WITHOUT max
// subtraction. 8 warps, warp tile = 16 rows x 64 cols. Double-buffered K in
// 128-row chunks (2 x 16KB; 8 syncs instead of 16). smem 48KB exact.
__global__ void __launch_bounds__(256) k_rowstats2() {
    __shared__ uint4 Qt[128 * 8];        // 16KB
    __shared__ uint4 Kt[2][128 * 8];     // 2 x 16KB

    int q0 = blockIdx.x * 128;
    int bh = blockIdx.y;
    int tid = threadIdx.x;
    int wid = tid >> 5, l = tid & 31;

    const uint4* qsrc = (const uint4*)(g_qh + ((size_t)bh * W_ + q0) * D_);
    #pragma unroll
    for (int i = 0; i < 4; i++) {
        int g = tid + i * 256;
        int r = g >> 3, c = g & 7;
        Qt[r * 8 + (c ^ (r & 7))] = qsrc[g];
    }

    float s0, z0, s1, z1, s3, z3;
    get_sz(0, s0, z0); get_sz(1, s1, z1); get_sz(3, s3, z3);
    float sc = s0 * s1 * 0.125f;
    float inv3 = 1.0f / s3;

    unsigned qbase = smem_u32(Qt);
    const uint4* ksrc = (const uint4*)(g_kh + (size_t)bh * W_ * D_);

    auto load_k = [&](int c, int buf) {   // 128 rows per chunk
        unsigned kb = smem_u32(Kt[buf]);
        #pragma unroll
        for (int i = 0; i < 4; i++) {
            int g = tid + i * 256;
            int r = g >> 3, cc = g & 7;
            cp_async16(kb + (r * 8 + (cc ^ (r & 7))) * 16, ksrc + (size_t)c * 1024 + g);
        }
        cp_async_commit();
    };

    load_k(0, 0);

    float sum0 = 0.0f, sum1 = 0.0f;
    float mx0 = -FLT_BIG, mx1 = -FLT_BIG, mn0 = FLT_BIG, mn1 = FLT_BIG;

    for (int c = 0; c < 8; c++) {
        int cur = c & 1;
        cp_async_wait0();
        __syncthreads();
        if (c < 7) load_k(c + 1, cur ^ 1);

        #pragma unroll
        for (int half = 0; half < 2; half++) {
            unsigned kbase = smem_u32(Kt[cur]) + half * (64 * 8 * 16);
            float acc[8][4];
            #pragma unroll
            for (int ni = 0; ni < 8; ni++)
                #pragma unroll
                for (int e = 0; e < 4; e++) acc[ni][e] = 0.0f;

            #pragma unroll
            for (int kc = 0; kc < 4; kc++) {
                unsigned a0, a1, a2, a3;
                {
                    int row = wid * 16 + (l & 15);
                    int ch  = kc * 2 + (l >> 4);
                    ldsm_x4(qbase + (row * 8 + (ch ^ (row & 7))) * 16, a0, a1, a2, a3);
                }
                #pragma unroll
                for (int ni = 0; ni < 8; ni++) {
                    unsigned b0, b1;
                    int row = ni * 8 + (l & 7);
                    int ch  = kc * 2 + ((l >> 3) & 1);
                    ldsm_x2(kbase + (row * 8 + (ch ^ (row & 7))) * 16, b0, b1);
                    mma16816(acc[ni], a0, a1, a2, a3, b0, b1);
                }
            }

            #pragma unroll
            for (int ni = 0; ni < 8; ni++) {
                float v00 = (fq_code(acc[ni][0] * sc, inv3, z3) - z3) * s3;
                float v01 = (fq_code(acc[ni][1] * sc, inv3, z3) - z3) * s3;
                float v10 = (fq_code(acc[ni][2] * sc, inv3, z3) - z3) * s3;
                float v11 = (fq_code(acc[ni][3] * sc, inv3, z3) - z3) * s3;
                sum0 += __expf(v00) + __expf(v01);
                sum1 += __expf(v10) + __expf(v11);
                mx0 = fmaxf(mx0, fmaxf(v00, v01)); mn0 = fminf(mn0, fminf(v00, v01));
                mx1 = fmaxf(mx1, fmaxf(v10, v11)); mn1 = fminf(mn1, fminf(v10, v11));
            }
        }
    }

    // single cross-lane reduction (4 lanes per row)
    #pragma unroll
    for (int o = 1; o <= 2; o <<= 1) {
        sum0 += __shfl_xor_sync(0xffffffffu, sum0, o);
        sum1 += __shfl_xor_sync(0xffffffffu, sum1, o);
        mx0 = fmaxf(mx0, __shfl_xor_sync(0xffffffffu, mx0, o));
        mx1 = fmaxf(mx1, __shfl_xor_sync(0xffffffffu, mx1, o));
        mn0 = fminf(mn0, __shfl_xor_sync(0xffffffffu, mn0, o));
        mn1 = fminf(mn1, __shfl_xor_sync(0xffffffffu, mn1, o));
    }
    float inv0 = 1.0f / sum0, inv1 = 1.0f / sum1;

    // att row extremes (exp monotone)
    float amin = fminf(__expf(mn0) * inv0, __expf(mn1) * inv1);
    float amax = fmaxf(__expf(mx0) * inv0, __expf(mx1) * inv1);
    warp_minmax_commit(amin, amax, 4, l);

    if ((l & 3) == 0) {
        int r0 = q0 + wid * 16 + (l >> 2);
        g_rowinv[(size_t)bh * W_ + r0]     = inv0;
        g_rowinv[(size_t)bh * W_ + r0 + 8] = inv1;
    }
}

// C: fused recompute-scores -> softmax (no max subtraction) -> fq att (write,
// streaming) -> att @ V -> ctx. 8 warps, warp tile = 16 q-rows x 64 cols; att
// ints repacked in registers. Double-buffered K/V. smem 48KB exact.
__global__ void __launch_bounds__(256) k_fusedav(float* __restrict__ att,
                                                 float* __restrict__ ctx) {
    __shared__ uint4 Qt[128 * 8];
    __shared__ uint4 Kt[2][64 * 8];
    __shared__ uint4 Vt[2][64 * 8];

    int q0 = blockIdx.x * 128;
    int bh = blockIdx.y;
    int b = bh >> 4, h = bh & 15;
    int tid = threadIdx.x;
    int wid = tid >> 5, l = tid & 31;

    const uint4* qsrc = (const uint4*)(g_qh + ((size_t)bh * W_ + q0) * D_);
    #pragma unroll
    for (int i = 0; i < 4; i++) {
        int g = tid + i * 256;
        int r = g >> 3, c = g & 7;
        Qt[r * 8 + (c ^ (r & 7))] = qsrc[g];
    }

    float s0, z0, s1, z1, s3, z3, s_a, zp_a, s_v, zp_v;
    get_sz(0, s0, z0); get_sz(1, s1, z1); get_sz(3, s3, z3);
    get_sz(4, s_a, zp_a); get_sz(2, s_v, zp_v);
    float sc = s0 * s1 * 0.125f;
    float inv3 = 1.0f / s3;
    float inv_a = 1.0f / s_a;

    // this warp's rows: r = wid*16 + (l>>2), and r+8
    float inv0 = g_rowinv[(size_t)bh * W_ + q0 + wid * 16 + (l >> 2)];
    float inv1 = g_rowinv[(size_t)bh * W_ + q0 + wid * 16 + (l >> 2) + 8];

    float cacc[8][4];
    #pragma unroll
    for (int i = 0; i < 8; i++)
        #pragma unroll
        for (int e = 0; e < 4; e++) cacc[i][e] = 0.0f;

    unsigned qbase = smem_u32(Qt);
    const uint4* ksrc = (const uint4*)(g_kh + (size_t)bh * W_ * D_);
    const uint4* vsrc = (const uint4*)(g_vh + (size_t)bh * W_ * D_);

    auto load_kv = [&](int kk, int buf) {
        unsigned kb = smem_u32(Kt[buf]);
        unsigned vb = smem_u32(Vt[buf]);
        #pragma unroll
        for (int i = 0; i < 2; i++) {
            int g = tid + i * 256;
            int r = g >> 3, c = g & 7;
            unsigned off = (r * 8 + (c ^ (r & 7))) * 16;
            cp_async16(kb + off, ksrc + (size_t)kk * 512 + g);
            cp_async16(vb + off, vsrc + (size_t)kk * 512 + g);
        }
        cp_async_commit();
    };

    load_kv(0, 0);

    float* att_base = att + ((size_t)bh * W_ + q0 + wid * 16 + (l >> 2)) * W_ + (l & 3) * 2;

    for (int kk = 0; kk < 16; kk++) {
        int cur = kk & 1;
        cp_async_wait0();
        __syncthreads();
        if (kk < 15) load_kv(kk + 1, cur ^ 1);

        unsigned kbase = smem_u32(Kt[cur]);
        unsigned vbase = smem_u32(Vt[cur]);

        // S = Q x K^T chunk: 16 rows x 64 cols per warp
        float sfr[8][4];
        #pragma unroll
        for (int ni = 0; ni < 8; ni++)
            #pragma unroll
            for (int e = 0; e < 4; e++) sfr[ni][e] = 0.0f;

        #pragma unroll
        for (int kc = 0; kc < 4; kc++) {
            unsigned a0, a1, a2, a3;
            {
                int row = wid * 16 + (l & 15);
                int ch  = kc * 2 + (l >> 4);
                ldsm_x4(qbase + (row * 8 + (ch ^ (row & 7))) * 16, a0, a1, a2, a3);
            }
            #pragma unroll
            for (int ni = 0; ni < 8; ni++) {
                unsigned b0, b1;
                int row = ni * 8 + (l & 7);
                int ch  = kc * 2 + ((l >> 3) & 1);
                ldsm_x2(kbase + (row * 8 + (ch ^ (row & 7))) * 16, b0, b1);
                mma16816(sfr[ni], a0, a1, a2, a3, b0, b1);
            }
        }

        // softmax + fq att; write att (streaming); repack ints into AV A-fragments
        unsigned amma[4][4];
        #pragma unroll
        for (int ni = 0; ni < 8; ni++) {
            float e0 = __expf((fq_code(sfr[ni][0] * sc, inv3, z3) - z3) * s3) * inv0;
            float e1 = __expf((fq_code(sfr[ni][1] * sc, inv3, z3) - z3) * s3) * inv0;
            float e2 = __expf((fq_code(sfr[ni][2] * sc, inv3, z3) - z3) * s3) * inv1;
            float e3 = __expf((fq_code(sfr[ni][3] * sc, inv3, z3) - z3) * s3) * inv1;
            float j0 = fq_q(e0, inv_a, zp_a), j1 = fq_q(e1, inv_a, zp_a);
            float j2 = fq_q(e2, inv_a, zp_a), j3 = fq_q(e3, inv_a, zp_a);
            stg_cs_f2(att_base + kk * 64 + ni * 8,          j0 * s_a, j1 * s_a);
            stg_cs_f2(att_base + 8 * W_ + kk * 64 + ni * 8, j2 * s_a, j3 * s_a);
            union { __half2 h2; unsigned u; } plo, phi;
            plo.h2 = __floats2half2_rn(j0, j1);
            phi.h2 = __floats2half2_rn(j2, j3);
            int kc = ni >> 1;
            if ((ni & 1) == 0) { amma[kc][0] = plo.u; amma[kc][1] = phi.u; }
            else               { amma[kc][2] = plo.u; amma[kc][3] = phi.u; }
        }

        // ctx += att(16x64) x V(64x64)
        #pragma unroll
        for (int kc = 0; kc < 4; kc++) {
            #pragma unroll
            for (int nt = 0; nt < 8; nt++) {
                unsigned b0, b1;
                int rv = kc * 16 + (l & 15);
                ldsm_x2t(vbase + (rv * 8 + (nt ^ (rv & 7))) * 16, b0, b1);
                mma16816(cacc[nt], amma[kc][0], amma[kc][1], amma[kc][2], amma[kc][3],
                         b0, b1);
            }
        }
    }

    float scv = s_a * s_v;
    float vmin = FLT_BIG, vmax = -FLT_BIG;
    int r0 = q0 + wid * 16 + (l >> 2);
    #pragma unroll
    for (int nt = 0; nt < 8; nt++) {
        int d = nt * 8 + (l & 3) * 2;
        float v0 = cacc[nt][0] * scv, v1 = cacc[nt][1] * scv;
        float v2 = cacc[nt][2] * scv, v3 = cacc[nt][3] * scv;
        vmin = fminf(vmin, fminf(fminf(v0, v1), fminf(v2, v3)));
        vmax = fmaxf(vmax, fmaxf(fmaxf(v0, v1), fmaxf(v2, v3)));
        size_t o0 = ((size_t)(b * W_ + r0) * H_ + h) * D_ + d;
        size_t o1 = ((size_t)(b * W_ + r0 + 8) * H_ + h) * D_ + d;
        *(float2*)(ctx + o0) = make_float2(v0, v1);
        *(float2*)(ctx + o1) = make_float2(v2, v3);
    }
    warp_minmax_commit(vmin, vmax, 5, l);
}

__global__ void __launch_bounds__(256) k_fqctx(float* __restrict__ ctx) {
    float s5, z5;
    get_sz(5, s5, z5);
    float inv5 = 1.0f / s5;
    for (int i = blockIdx.x * blockDim.x + threadIdx.x; i < NQKV; i += gridDim.x * blockDim.x) {
        ctx[i] = fq_q(ctx[i], inv5, z5) * s5;
    }
}

// ---------------- launch ----------------
extern "C" void kernel_launch(void* const* d_in, const int* in_sizes, int n_in,
                              void* d_out, int out_size) {
    const float* q = (const float*)d_in[0];
    const float* k = (const float*)d_in[1];
    const float* v = (const float*)d_in[2];

    float* ctx = (float*)d_out;
    float* att = (float*)d_out + ((size_t)out_size - NATT);

    k_init<<<1, 32>>>();

    k_minmax3<<<1536, 256>>>((const float4*)q, (const float4*)k, (const float4*)v);

    k_quant<<<B_ * W_, 256>>>(q, k, v);

    dim3 ga(8, 8, BH_);
    k_sminmax<<<ga, 256>>>();

    dim3 gb(8, BH_);
    k_rowstats2<<<gb, 256>>>();

    dim3 gc(8, BH_);
    k_fusedav<<<gc, 256>>>(att, ctx);

    k_fqctx<<<2048, 256>>>(ctx);
}